// round 12
// baseline (speedup 1.0000x reference)
#include <cuda_runtime.h>

#define H 4096
#define E 8
#define H4 1024                 // float4 per row
#define TPB 256
#define NROUTER E               // 8 dedicated router blocks
#define GRID (H + NROUTER)      // 4104
#define ITERS (H4 / TPB)        // 4

__device__ unsigned long long g_best;  // (sortable_logit << 32) | (7 - e); 0 == -inf sentinel
__device__ int g_rcnt;                 // router blocks completed (0..8)
__device__ int g_done;                 // blocks finished (self-reset)

__device__ __forceinline__ unsigned int f2sortable(float f) {
    unsigned int u = __float_as_uint(f);
    return (u & 0x80000000u) ? ~u : (u | 0x80000000u);
}

__global__ void __launch_bounds__(TPB) fused_kernel(
    const float* __restrict__ x,
    const float* __restrict__ expert_w,
    const float* __restrict__ expert_b,
    const float* __restrict__ router_w,
    const float* __restrict__ router_b,
    const float* __restrict__ gate_w,
    const float* __restrict__ gate_b,
    float* __restrict__ out) {

    const int wid  = threadIdx.x >> 5;
    const int lane = threadIdx.x & 31;
    const float4* x4 = (const float4*)x;

    // ---- Blocks 0..7: router ONLY (16 KB dot each), then exit.
    //      Scheduled first (lowest bids) -> resident in wave 1, finish in ~3us.
    if (blockIdx.x < NROUTER) {
        const int e = blockIdx.x;
        const float4* w4 = (const float4*)(router_w + (size_t)e * H);
        float s = 0.f;
        #pragma unroll
        for (int k = 0; k < ITERS; k++) {
            int i = threadIdx.x + k * TPB;
            float4 a = x4[i];
            float4 b = w4[i];
            s += a.x * b.x + a.y * b.y + a.z * b.z + a.w * b.w;
        }
        #pragma unroll
        for (int o = 16; o > 0; o >>= 1) s += __shfl_xor_sync(0xFFFFFFFFu, s, o);

        __shared__ float s_red[TPB / 32];
        if (lane == 0) s_red[wid] = s;
        __syncthreads();
        if (threadIdx.x == 0) {
            float v = router_b[e];
            #pragma unroll
            for (int w = 0; w < TPB / 32; w++) v += s_red[w];
            unsigned long long key =
                ((unsigned long long)f2sortable(v) << 32) | (unsigned long long)(7 - e);
            atomicMax(&g_best, key);
            __threadfence();
            atomicAdd(&g_rcnt, 1);
            // participate in the self-reset protocol
            int d = atomicAdd(&g_done, 1);
            if (d == GRID - 1) { g_done = 0; g_rcnt = 0; g_best = 0ULL; __threadfence(); }
        }
        return;
    }

    // ---- Row blocks: one output row each (R2 shape) ----
    const int row = blockIdx.x - NROUTER;

    // Phase 1: gate dot — 8 loads batched up front (4x x + 4x gate)
    const float4* g4 = (const float4*)(gate_w + (size_t)row * H);
    float4 xa[ITERS], ga[ITERS];
    #pragma unroll
    for (int k = 0; k < ITERS; k++) {
        int i = threadIdx.x + k * TPB;
        xa[k] = x4[i];
        ga[k] = g4[i];
    }
    float sg = 0.f;
    #pragma unroll
    for (int k = 0; k < ITERS; k++) {
        sg += xa[k].x * ga[k].x + xa[k].y * ga[k].y
            + xa[k].z * ga[k].z + xa[k].w * ga[k].w;
    }

    // Poll router result — gate phase (~12us of streaming behind us across the
    // grid) >> router time (~3us), so this is a single read in steady state.
    int idx;
    if (lane == 0) {
        while (*(volatile int*)&g_rcnt < E) { __nanosleep(32); }
        __threadfence();
        unsigned long long b = *(volatile unsigned long long*)&g_best;
        idx = 7 - (int)(b & 7ULL);
    }
    idx = __shfl_sync(0xFFFFFFFFu, idx, 0);

    // Phase 2: expert dot — 4 loads batched, xa reused
    const float4* e4 = (const float4*)(expert_w + ((size_t)idx * H + row) * H);
    float4 ea[ITERS];
    #pragma unroll
    for (int k = 0; k < ITERS; k++) {
        int i = threadIdx.x + k * TPB;
        ea[k] = e4[i];
    }
    float se = 0.f;
    #pragma unroll
    for (int k = 0; k < ITERS; k++) {
        se += xa[k].x * ea[k].x + xa[k].y * ea[k].y
            + xa[k].z * ea[k].z + xa[k].w * ea[k].w;
    }

    // Reductions (R2 pattern)
    #pragma unroll
    for (int o = 16; o > 0; o >>= 1) {
        sg += __shfl_xor_sync(0xFFFFFFFFu, sg, o);
        se += __shfl_xor_sync(0xFFFFFFFFu, se, o);
    }

    __shared__ float re[TPB / 32], rg[TPB / 32];
    if (lane == 0) { re[wid] = se; rg[wid] = sg; }
    __syncthreads();

    if (threadIdx.x == 0) {
        float SE = 0.f, SG = 0.f;
        #pragma unroll
        for (int w = 0; w < TPB / 32; w++) { SE += re[w]; SG += rg[w]; }
        float mix = tanhf(SE + expert_b[(size_t)idx * H + row]);
        float z = SG + gate_b[row];
        float g = 1.f / (1.f + expf(-z));
        float xv = x[row];
        out[row] = g * mix + (1.f - g) * xv;

        // self-reset protocol
        int d = atomicAdd(&g_done, 1);
        if (d == GRID - 1) { g_done = 0; g_rcnt = 0; g_best = 0ULL; __threadfence(); }
    }
}

extern "C" void kernel_launch(void* const* d_in, const int* in_sizes, int n_in,
                              void* d_out, int out_size) {
    const float* x        = (const float*)d_in[0];  // [1, H]
    const float* expert_w = (const float*)d_in[1];  // [E, H, H]
    const float* expert_b = (const float*)d_in[2];  // [E, H]
    const float* router_w = (const float*)d_in[3];  // [E, H]
    const float* router_b = (const float*)d_in[4];  // [E]
    const float* gate_w   = (const float*)d_in[5];  // [H, H]
    const float* gate_b   = (const float*)d_in[6];  // [H]
    float* out = (float*)d_out;                     // [1, H]

    fused_kernel<<<GRID, TPB>>>(x, expert_w, expert_b, router_w, router_b,
                                gate_w, gate_b, out);
}

// round 13
// speedup vs baseline: 1.2522x; 1.2522x over previous
#include <cuda_runtime.h>
#include <cstdint>

#define H 4096
#define E 8
#define H4 1024                 // float4 per row
#define TPB 256
#define ITERS (H4 / TPB)        // 4
#define ROW_BYTES (H * 4)       // 16384

__device__ unsigned long long g_best;  // (sortable_logit << 32) | (7 - e)
__device__ int g_rcnt;
__device__ int g_idx;

__device__ __forceinline__ unsigned int f2sortable(float f) {
    unsigned int u = __float_as_uint(f);
    return (u & 0x80000000u) ? ~u : (u | 0x80000000u);
}

__device__ __forceinline__ uint32_t smem_u32(const void* p) {
    uint32_t a;
    asm("{ .reg .u64 t; cvta.to.shared.u64 t, %1; cvt.u32.u64 %0, t; }"
        : "=r"(a) : "l"(p));
    return a;
}

// ---- Kernel 1: router, 8 blocks (one expert each). Last block decodes
//      argmax into g_idx and resets the scratch state for the next replay.
__global__ void __launch_bounds__(TPB) router_kernel(
        const float* __restrict__ x,
        const float* __restrict__ router_w,
        const float* __restrict__ router_b) {
    const int e    = blockIdx.x;
    const int wid  = threadIdx.x >> 5;
    const int lane = threadIdx.x & 31;
    const float4* x4 = (const float4*)x;
    const float4* w4 = (const float4*)(router_w + (size_t)e * H);

    float s = 0.f;
    #pragma unroll
    for (int k = 0; k < ITERS; k++) {
        int i = threadIdx.x + k * TPB;
        float4 a = x4[i];
        float4 b = w4[i];
        s += a.x * b.x + a.y * b.y + a.z * b.z + a.w * b.w;
    }
    #pragma unroll
    for (int o = 16; o > 0; o >>= 1) s += __shfl_xor_sync(0xFFFFFFFFu, s, o);

    __shared__ float s_red[TPB / 32];
    if (lane == 0) s_red[wid] = s;
    __syncthreads();
    if (threadIdx.x == 0) {
        float v = router_b[e];
        #pragma unroll
        for (int w = 0; w < TPB / 32; w++) v += s_red[w];
        unsigned long long key =
            ((unsigned long long)f2sortable(v) << 32) | (unsigned long long)(7 - e);
        atomicMax(&g_best, key);
        __threadfence();
        int r = atomicAdd(&g_rcnt, 1);
        if (r == E - 1) {                      // last router block: decode + reset
            __threadfence();
            unsigned long long b = atomicAdd(&g_best, 0ULL);
            g_idx = 7 - (int)(b & 7ULL);
            g_best = 0ULL;
            g_rcnt = 0;
            __threadfence();
        }
    }
}

// ---- Kernel 2: one block per row. Two 16 KB cp.async.bulk copies into smem
//      (gate row + chosen expert row), overlap x loads, dot from smem.
__global__ void __launch_bounds__(TPB) gate_mix_kernel(
    const float* __restrict__ x,
    const float* __restrict__ expert_w,
    const float* __restrict__ expert_b,
    const float* __restrict__ gate_w,
    const float* __restrict__ gate_b,
    float* __restrict__ out) {

    __shared__ alignas(16) float s_gate[H];          // 16 KB
    __shared__ alignas(16) float s_exp[H];           // 16 KB
    __shared__ alignas(8)  unsigned long long s_mbar;

    const int row  = blockIdx.x;
    const int wid  = threadIdx.x >> 5;
    const int lane = threadIdx.x & 31;
    const int idx  = g_idx;                          // uniform, set by kernel 1

    const uint32_t mb = smem_u32(&s_mbar);

    if (threadIdx.x == 0) {
        asm volatile("mbarrier.init.shared.b64 [%0], 1;" :: "r"(mb) : "memory");
    }
    __syncthreads();

    if (threadIdx.x == 0) {
        asm volatile("mbarrier.arrive.expect_tx.shared.b64 _, [%0], %1;"
                     :: "r"(mb), "r"(2 * ROW_BYTES) : "memory");
        const float* gsrc = gate_w + (size_t)row * H;
        const float* esrc = expert_w + ((size_t)idx * H + row) * H;
        asm volatile(
            "cp.async.bulk.shared::cta.global.mbarrier::complete_tx::bytes "
            "[%0], [%1], %2, [%3];"
            :: "r"(smem_u32(s_gate)), "l"(gsrc), "r"(ROW_BYTES), "r"(mb) : "memory");
        asm volatile(
            "cp.async.bulk.shared::cta.global.mbarrier::complete_tx::bytes "
            "[%0], [%1], %2, [%3];"
            :: "r"(smem_u32(s_exp)), "l"(esrc), "r"(ROW_BYTES), "r"(mb) : "memory");
    }

    // Overlap: load x (L1/L2-hot) while the bulk copies are in flight.
    const float4* x4 = (const float4*)x;
    float4 xa[ITERS];
    #pragma unroll
    for (int k = 0; k < ITERS; k++) xa[k] = x4[threadIdx.x + k * TPB];

    // Wait for both copies (acquire orders subsequent smem reads).
    asm volatile(
        "{\n\t"
        ".reg .pred p;\n\t"
        "WL_%=:\n\t"
        "mbarrier.try_wait.parity.acquire.cta.shared::cta.b64 p, [%0], 0;\n\t"
        "@p bra WD_%=;\n\t"
        "bra WL_%=;\n\t"
        "WD_%=:\n\t"
        "}"
        :: "r"(mb) : "memory");

    const float4* sg4 = (const float4*)s_gate;
    const float4* se4 = (const float4*)s_exp;
    float sg = 0.f, se = 0.f;
    #pragma unroll
    for (int k = 0; k < ITERS; k++) {
        int i = threadIdx.x + k * TPB;
        float4 g = sg4[i];
        float4 e = se4[i];
        sg += xa[k].x * g.x + xa[k].y * g.y + xa[k].z * g.z + xa[k].w * g.w;
        se += xa[k].x * e.x + xa[k].y * e.y + xa[k].z * e.z + xa[k].w * e.w;
    }

    #pragma unroll
    for (int o = 16; o > 0; o >>= 1) {
        sg += __shfl_xor_sync(0xFFFFFFFFu, sg, o);
        se += __shfl_xor_sync(0xFFFFFFFFu, se, o);
    }

    __shared__ float re[TPB / 32], rg[TPB / 32];
    if (lane == 0) { re[wid] = se; rg[wid] = sg; }
    __syncthreads();

    if (threadIdx.x == 0) {
        float SE = 0.f, SG = 0.f;
        #pragma unroll
        for (int w = 0; w < TPB / 32; w++) { SE += re[w]; SG += rg[w]; }
        float mix = tanhf(SE + expert_b[(size_t)idx * H + row]);
        float z = SG + gate_b[row];
        float g = 1.f / (1.f + expf(-z));
        float xv = x[row];
        out[row] = g * mix + (1.f - g) * xv;
    }
}

extern "C" void kernel_launch(void* const* d_in, const int* in_sizes, int n_in,
                              void* d_out, int out_size) {
    const float* x        = (const float*)d_in[0];  // [1, H]
    const float* expert_w = (const float*)d_in[1];  // [E, H, H]
    const float* expert_b = (const float*)d_in[2];  // [E, H]
    const float* router_w = (const float*)d_in[3];  // [E, H]
    const float* router_b = (const float*)d_in[4];  // [E]
    const float* gate_w   = (const float*)d_in[5];  // [H, H]
    const float* gate_b   = (const float*)d_in[6];  // [H]
    float* out = (float*)d_out;                     // [1, H]

    router_kernel<<<E, TPB>>>(x, router_w, router_b);
    gate_mix_kernel<<<H, TPB>>>(x, expert_w, expert_b, gate_w, gate_b, out);
}

// round 14
// speedup vs baseline: 1.2645x; 1.0099x over previous
#include <cuda_runtime.h>
#include <cstdint>

#define H 4096
#define E 8
#define H4 1024                 // float4 per row
#define TPB 256
#define ITERS (H4 / TPB)        // 4
#define ROW_BYTES (H * 4)       // 16384
#define GRIDN 444               // 3 blocks/SM * 148 SMs -> fully resident
#define STAGE_FLOATS (2 * H)    // gate row + expert row per stage
#define SMEM_BYTES (2 * STAGE_FLOATS * 4 + 128)   // 2 stages + mbarriers

__device__ unsigned long long g_best;  // (sortable_logit << 32) | (7 - e)
__device__ int g_rcnt;
__device__ int g_idx;

__device__ __forceinline__ unsigned int f2sortable(float f) {
    unsigned int u = __float_as_uint(f);
    return (u & 0x80000000u) ? ~u : (u | 0x80000000u);
}

__device__ __forceinline__ uint32_t smem_u32(const void* p) {
    uint32_t a;
    asm("{ .reg .u64 t; cvta.to.shared.u64 t, %1; cvt.u32.u64 %0, t; }"
        : "=r"(a) : "l"(p));
    return a;
}

__device__ __forceinline__ void mbar_wait(uint32_t mb, int parity) {
    asm volatile(
        "{\n\t"
        ".reg .pred p;\n\t"
        "WL_%=:\n\t"
        "mbarrier.try_wait.parity.acquire.cta.shared::cta.b64 p, [%0], %1;\n\t"
        "@p bra WD_%=;\n\t"
        "bra WL_%=;\n\t"
        "WD_%=:\n\t"
        "}"
        :: "r"(mb), "r"(parity) : "memory");
}

// ---- Kernel 1: router, 8 blocks (one expert each); last block decodes + resets.
__global__ void __launch_bounds__(TPB) router_kernel(
        const float* __restrict__ x,
        const float* __restrict__ router_w,
        const float* __restrict__ router_b) {
    const int e    = blockIdx.x;
    const int wid  = threadIdx.x >> 5;
    const int lane = threadIdx.x & 31;
    const float4* x4 = (const float4*)x;
    const float4* w4 = (const float4*)(router_w + (size_t)e * H);

    float s = 0.f;
    #pragma unroll
    for (int k = 0; k < ITERS; k++) {
        int i = threadIdx.x + k * TPB;
        float4 a = x4[i];
        float4 b = w4[i];
        s += a.x * b.x + a.y * b.y + a.z * b.z + a.w * b.w;
    }
    #pragma unroll
    for (int o = 16; o > 0; o >>= 1) s += __shfl_xor_sync(0xFFFFFFFFu, s, o);

    __shared__ float s_red[TPB / 32];
    if (lane == 0) s_red[wid] = s;
    __syncthreads();
    if (threadIdx.x == 0) {
        float v = router_b[e];
        #pragma unroll
        for (int w = 0; w < TPB / 32; w++) v += s_red[w];
        unsigned long long key =
            ((unsigned long long)f2sortable(v) << 32) | (unsigned long long)(7 - e);
        atomicMax(&g_best, key);
        __threadfence();
        int r = atomicAdd(&g_rcnt, 1);
        if (r == E - 1) {
            __threadfence();
            unsigned long long b = atomicAdd(&g_best, 0ULL);
            g_idx = 7 - (int)(b & 7ULL);
            g_best = 0ULL;
            g_rcnt = 0;
            __threadfence();
        }
    }
}

// ---- Kernel 2: persistent blocks, double-buffered TMA pipeline over rows.
__global__ void __launch_bounds__(TPB) gate_mix_kernel(
    const float* __restrict__ x,
    const float* __restrict__ expert_w,
    const float* __restrict__ expert_b,
    const float* __restrict__ gate_w,
    const float* __restrict__ gate_b,
    float* __restrict__ out) {

    extern __shared__ float smem[];
    float* buf0 = smem;                         // [gate 4096 | expert 4096]
    float* buf1 = smem + STAGE_FLOATS;
    unsigned long long* mbars =
        (unsigned long long*)(smem + 2 * STAGE_FLOATS);
    const uint32_t mb0 = smem_u32(&mbars[0]);
    const uint32_t mb1 = smem_u32(&mbars[1]);

    const int wid  = threadIdx.x >> 5;
    const int lane = threadIdx.x & 31;
    const int idx  = g_idx;                     // uniform, set by kernel 1

    if (threadIdx.x == 0) {
        asm volatile("mbarrier.init.shared.b64 [%0], 1;" :: "r"(mb0) : "memory");
        asm volatile("mbarrier.init.shared.b64 [%0], 1;" :: "r"(mb1) : "memory");
    }
    __syncthreads();

    const float* ew_base = expert_w + (size_t)idx * H * H;

    // issue both 16 KB copies for `row` into stage (thread 0 only)
    auto issue = [&](float* buf, uint32_t mb, int row) {
        asm volatile("mbarrier.arrive.expect_tx.shared.b64 _, [%0], %1;"
                     :: "r"(mb), "r"(2 * ROW_BYTES) : "memory");
        asm volatile(
            "cp.async.bulk.shared::cta.global.mbarrier::complete_tx::bytes "
            "[%0], [%1], %2, [%3];"
            :: "r"(smem_u32(buf)), "l"(gate_w + (size_t)row * H),
               "r"(ROW_BYTES), "r"(mb) : "memory");
        asm volatile(
            "cp.async.bulk.shared::cta.global.mbarrier::complete_tx::bytes "
            "[%0], [%1], %2, [%3];"
            :: "r"(smem_u32(buf + H)), "l"(ew_base + (size_t)row * H),
               "r"(ROW_BYTES), "r"(mb) : "memory");
    };

    // x: loaded once into registers, reused for every row
    const float4* x4 = (const float4*)x;
    float4 xa[ITERS];
    #pragma unroll
    for (int k = 0; k < ITERS; k++) xa[k] = x4[threadIdx.x + k * TPB];

    __shared__ float re[TPB / 32], rg[TPB / 32];

    // compute one row from a stage buffer + epilogue
    auto compute = [&](const float* buf, int row) {
        const float4* g4 = (const float4*)buf;
        const float4* e4 = (const float4*)(buf + H);
        float sg = 0.f, se = 0.f;
        #pragma unroll
        for (int k = 0; k < ITERS; k++) {
            int i = threadIdx.x + k * TPB;
            float4 g = g4[i];
            float4 e = e4[i];
            sg += xa[k].x * g.x + xa[k].y * g.y + xa[k].z * g.z + xa[k].w * g.w;
            se += xa[k].x * e.x + xa[k].y * e.y + xa[k].z * e.z + xa[k].w * e.w;
        }
        #pragma unroll
        for (int o = 16; o > 0; o >>= 1) {
            sg += __shfl_xor_sync(0xFFFFFFFFu, sg, o);
            se += __shfl_xor_sync(0xFFFFFFFFu, se, o);
        }
        if (lane == 0) { re[wid] = se; rg[wid] = sg; }
        __syncthreads();                         // all buf reads done here
        if (threadIdx.x == 0) {
            float SE = 0.f, SG = 0.f;
            #pragma unroll
            for (int w = 0; w < TPB / 32; w++) { SE += re[w]; SG += rg[w]; }
            float mix = tanhf(SE + expert_b[(size_t)idx * H + row]);
            float z = SG + gate_b[row];
            float gg = 1.f / (1.f + expf(-z));
            float xv = x[row];
            out[row] = gg * mix + (1.f - gg) * xv;
        }
        __syncthreads();                         // protect re/rg reuse
    };

    int row = blockIdx.x;
    if (row >= H) return;

    if (threadIdx.x == 0) {
        issue(buf0, mb0, row);
        if (row + GRIDN < H) issue(buf1, mb1, row + GRIDN);
    }

    int p0 = 0, p1 = 0;
    while (true) {
        // stage 0
        mbar_wait(mb0, p0); p0 ^= 1;
        compute(buf0, row);
        if (threadIdx.x == 0 && row + 2 * GRIDN < H)
            issue(buf0, mb0, row + 2 * GRIDN);
        row += GRIDN;
        if (row >= H) break;

        // stage 1
        mbar_wait(mb1, p1); p1 ^= 1;
        compute(buf1, row);
        if (threadIdx.x == 0 && row + 2 * GRIDN < H)
            issue(buf1, mb1, row + 2 * GRIDN);
        row += GRIDN;
        if (row >= H) break;
    }
}

extern "C" void kernel_launch(void* const* d_in, const int* in_sizes, int n_in,
                              void* d_out, int out_size) {
    const float* x        = (const float*)d_in[0];  // [1, H]
    const float* expert_w = (const float*)d_in[1];  // [E, H, H]
    const float* expert_b = (const float*)d_in[2];  // [E, H]
    const float* router_w = (const float*)d_in[3];  // [E, H]
    const float* router_b = (const float*)d_in[4];  // [E]
    const float* gate_w   = (const float*)d_in[5];  // [H, H]
    const float* gate_b   = (const float*)d_in[6];  // [H]
    float* out = (float*)d_out;                     // [1, H]

    static bool attr_set = false;
    if (!attr_set) {
        cudaFuncSetAttribute(gate_mix_kernel,
                             cudaFuncAttributeMaxDynamicSharedMemorySize,
                             SMEM_BYTES);
        attr_set = true;
    }

    router_kernel<<<E, TPB>>>(x, router_w, router_b);
    gate_mix_kernel<<<GRIDN, TPB, SMEM_BYTES>>>(x, expert_w, expert_b,
                                                gate_w, gate_b, out);
}